// round 1
// baseline (speedup 1.0000x reference)
#include <cuda_runtime.h>
#include <cuda_bf16.h>

#define NB   16
#define TQ   128
#define TK   256
#define DIN  64
#define HH   256
#define DV   256
#define NEGV -1000000.0f
#define QT   4

// Scratch for projected Q and K (device globals: allowed, no allocation).
__device__ float g_qproj[NB * TQ * HH];   // 2 MB
__device__ float g_kproj[NB * TK * HH];   // 4 MB

__device__ __forceinline__ float tanh_fast(float x) {
    float y;
    asm("tanh.approx.f32 %0, %1;" : "=f"(y) : "f"(x));
    return y;
}

// ---------------------------------------------------------------------------
// Kernel 1: row-blocked projections. rows [0,2048) = queries @ wq,
// rows [0,4096) of keys @ wk. Each block: RPROJ rows, weights staged in smem
// in two 32-row d-chunks (stays under 48KB static smem).
// ---------------------------------------------------------------------------
#define RPROJ 16
__global__ __launch_bounds__(256) void proj_kernel(
    const float* __restrict__ queries, const float* __restrict__ keys,
    const float* __restrict__ wq, const float* __restrict__ wk)
{
    __shared__ float wsm[32][HH];           // 32 KB
    __shared__ float insm[RPROJ][DIN];      // 4 KB

    const int tid = threadIdx.x;
    const int blk = blockIdx.x;
    const int QBLK = NB * TQ / RPROJ;       // 128 q-blocks, then 256 k-blocks

    const float* w;
    const float* in;
    float* outp;
    if (blk < QBLK) {
        int row0 = blk * RPROJ;
        w = wq; in = queries + row0 * DIN; outp = g_qproj + row0 * HH;
    } else {
        int row0 = (blk - QBLK) * RPROJ;
        w = wk; in = keys + row0 * DIN; outp = g_kproj + row0 * HH;
    }

    // stage input rows (RPROJ*DIN = 1024 floats = 256 float4)
    ((float4*)insm)[tid] = ((const float4*)in)[tid];

    float acc[RPROJ];
#pragma unroll
    for (int r = 0; r < RPROJ; r++) acc[r] = 0.f;

    for (int dc = 0; dc < 2; dc++) {
        __syncthreads();                               // insm ready / wsm free
        const float4* w4 = (const float4*)(w + dc * 32 * HH);
        float4* wsm4 = (float4*)wsm;
#pragma unroll
        for (int i = 0; i < 8; i++) wsm4[tid + i * 256] = w4[tid + i * 256];
        __syncthreads();
#pragma unroll
        for (int d = 0; d < 32; d++) {
            float wval = wsm[d][tid];                  // lanes: consecutive h, conflict-free
#pragma unroll
            for (int r = 0; r < RPROJ; r++)
                acc[r] += insm[r][dc * 32 + d] * wval; // broadcast
        }
    }
#pragma unroll
    for (int r = 0; r < RPROJ; r++) outp[r * HH + tid] = acc[r];
}

// ---------------------------------------------------------------------------
// Kernel 2: fused scores (tanh-additive) + masked softmax + attn @ values.
// One block per (b, 4-query tile): 512 blocks x 256 threads, thread = k column.
// K-proj staged in smem h-major as float4 (4 h per element) so the hot loop
// is one conflict-free LDS.128 per 4 tanh per thread; q/wv are broadcasts.
// ---------------------------------------------------------------------------
__global__ __launch_bounds__(256) void attn_kernel(
    const float* __restrict__ values, const int* __restrict__ valid_lens,
    const float* __restrict__ wv, float* __restrict__ out)
{
    __shared__ float4 ksm[8][259];     // [h4][k], padded row -> conflict-free STS
    __shared__ float4 qsm[8][QT];      // [h4][qi]
    __shared__ float4 wvs[8];          // [h4]
    __shared__ float  scr[QT][264];    // scores [qi][k]
    __shared__ float4 attnT[TK];       // attn [k] as float4 over qi

    const int tid = threadIdx.x;
    const int b  = blockIdx.x >> 5;
    const int qt = blockIdx.x & 31;

    const float4* kp4 = (const float4*)(g_kproj + b * TK * HH);
    const float4* qp4 = (const float4*)(g_qproj + (b * TQ + qt * QT) * HH);
    const float4* wv4 = (const float4*)wv;

    float acc[QT] = {0.f, 0.f, 0.f, 0.f};

    for (int hc = 0; hc < 8; hc++) {   // h in chunks of 32
        // stage K chunk: 256 k x 8 float4, coalesced global reads,
        // transposed (h-major) smem writes, pad 259 kills STS conflicts
#pragma unroll
        for (int i = 0; i < 8; i++) {
            int idx = tid + i * 256;
            int k = idx >> 3, j = idx & 7;
            ksm[j][k] = kp4[k * 64 + hc * 8 + j];
        }
        if (tid < 8 * QT) {
            int qi = tid >> 3, j = tid & 7;
            qsm[j][qi] = qp4[qi * 64 + hc * 8 + j];
        }
        if (tid < 8) wvs[tid] = wv4[hc * 8 + tid];
        __syncthreads();

#pragma unroll
        for (int j = 0; j < 8; j++) {
            float4 kv = ksm[j][tid];   // conflict-free LDS.128
            float4 w4 = wvs[j];        // broadcast
#pragma unroll
            for (int qi = 0; qi < QT; qi++) {
                float4 qv = qsm[j][qi];  // broadcast
                acc[qi] += w4.x * tanh_fast(qv.x + kv.x);
                acc[qi] += w4.y * tanh_fast(qv.y + kv.y);
                acc[qi] += w4.z * tanh_fast(qv.z + kv.z);
                acc[qi] += w4.w * tanh_fast(qv.w + kv.w);
            }
        }
        __syncthreads();
    }

    // mask + stage scores
    const int valid = valid_lens[b];
    const bool on = (tid < valid);
#pragma unroll
    for (int qi = 0; qi < QT; qi++) scr[qi][tid] = on ? acc[qi] : NEGV;
    __syncthreads();

    // per-warp softmax: warp w handles query row w (QT=4 rows, warps 4-7 idle)
    const int warp = tid >> 5, lane = tid & 31;
    if (warp < QT) {
        float v[8];
        float m = -3.0e38f;
#pragma unroll
        for (int j = 0; j < 8; j++) {
            v[j] = scr[warp][lane + 32 * j];
            m = fmaxf(m, v[j]);
        }
#pragma unroll
        for (int o = 16; o > 0; o >>= 1) m = fmaxf(m, __shfl_xor_sync(0xffffffffu, m, o));
        float s = 0.f;
#pragma unroll
        for (int j = 0; j < 8; j++) { v[j] = __expf(v[j] - m); s += v[j]; }
#pragma unroll
        for (int o = 16; o > 0; o >>= 1) s += __shfl_xor_sync(0xffffffffu, s, o);
        const float inv = 1.f / s;
        float* at = (float*)attnT;
#pragma unroll
        for (int j = 0; j < 8; j++) at[(lane + 32 * j) * 4 + warp] = v[j] * inv;
    }
    __syncthreads();

    // AV: thread = value column v = tid. 1 coalesced LDG + 1 broadcast LDS.128
    // + 4 FMA per k.
    float o4[QT] = {0.f, 0.f, 0.f, 0.f};
    const float* vp = values + b * TK * DV + tid;
#pragma unroll 4
    for (int k = 0; k < TK; k++) {
        float vv = vp[k * DV];
        float4 a = attnT[k];
        o4[0] += a.x * vv;
        o4[1] += a.y * vv;
        o4[2] += a.z * vv;
        o4[3] += a.w * vv;
    }
    float* op = out + (b * TQ + qt * QT) * DV + tid;
#pragma unroll
    for (int qi = 0; qi < QT; qi++) op[qi * DV] = o4[qi];
}

// ---------------------------------------------------------------------------
extern "C" void kernel_launch(void* const* d_in, const int* in_sizes, int n_in,
                              void* d_out, int out_size) {
    const float* queries    = (const float*)d_in[0];
    const float* keys       = (const float*)d_in[1];
    const float* values     = (const float*)d_in[2];
    const int*   valid_lens = (const int*)  d_in[3];
    const float* wq         = (const float*)d_in[4];
    const float* wk         = (const float*)d_in[5];
    const float* wv         = (const float*)d_in[6];
    float* out = (float*)d_out;

    proj_kernel<<<384, 256>>>(queries, keys, wq, wk);
    attn_kernel<<<NB * (TQ / QT), 256>>>(values, valid_lens, wv, out);
}

// round 6
// speedup vs baseline: 1.1064x; 1.1064x over previous
#include <cuda_runtime.h>
#include <cuda_bf16.h>

#define NB   16
#define TQ   128
#define TK   256
#define DIN  64
#define HH   256
#define DV   256
#define NEGV -1000000.0f
#define QT   4

// Scratch (device globals: allowed, no allocation).
__device__ float g_qproj[NB * TQ * HH];        // [b][q][h]  row-major, 2 MB
__device__ float g_kprojT[NB * HH * TK];       // [b][h][k]  h-major,   4 MB

__device__ __forceinline__ float tanh_fast(float x) {
    float y;
    asm("tanh.approx.f32 %0, %1;" : "=f"(y) : "f"(x));
    return y;
}

// ---------------------------------------------------------------------------
// Kernel 1: projections. Blocks [0,128): queries @ wq -> g_qproj (row-major).
// Blocks [128,384): keys @ wk -> g_kprojT (TRANSPOSED, h-major) via an smem
// transpose so global writes stay reasonably coalesced (64B segments).
// ---------------------------------------------------------------------------
#define RPROJ 16
__global__ __launch_bounds__(256) void proj_kernel(
    const float* __restrict__ queries, const float* __restrict__ keys,
    const float* __restrict__ wq, const float* __restrict__ wk)
{
    __shared__ float wsm[32][HH];           // 32 KB (reused as transpose buffer)
    __shared__ float insm[RPROJ][DIN];      // 4 KB

    const int tid = threadIdx.x;
    const int blk = blockIdx.x;
    const int QBLK = NB * TQ / RPROJ;       // 128

    const bool is_q = (blk < QBLK);
    const int  rblk = is_q ? blk : (blk - QBLK);
    const int  row0 = rblk * RPROJ;
    const float* w  = is_q ? wq : wk;
    const float* in = (is_q ? queries : keys) + row0 * DIN;

    // stage input rows (RPROJ*DIN = 1024 floats = 256 float4)
    ((float4*)insm)[tid] = ((const float4*)in)[tid];

    float acc[RPROJ];
#pragma unroll
    for (int r = 0; r < RPROJ; r++) acc[r] = 0.f;

    for (int dc = 0; dc < 2; dc++) {
        __syncthreads();
        const float4* w4 = (const float4*)(w + dc * 32 * HH);
        float4* wsm4 = (float4*)wsm;
#pragma unroll
        for (int i = 0; i < 8; i++) wsm4[tid + i * 256] = w4[tid + i * 256];
        __syncthreads();
#pragma unroll
        for (int d = 0; d < 32; d++) {
            float wval = wsm[d][tid];                  // conflict-free
#pragma unroll
            for (int r = 0; r < RPROJ; r++)
                acc[r] += insm[r][dc * 32 + d] * wval; // broadcast
        }
    }

    if (is_q) {
        float* outp = g_qproj + row0 * HH;
#pragma unroll
        for (int r = 0; r < RPROJ; r++) outp[r * HH + tid] = acc[r];
    } else {
        // transpose 16 rows x 256 h through smem, write h-major
        __syncthreads();                    // wsm reads complete
        float* tsm = (float*)wsm;           // [r][h] = tsm[r*HH + h]
#pragma unroll
        for (int r = 0; r < RPROJ; r++) tsm[r * HH + tid] = acc[r];
        __syncthreads();

        const int b  = row0 / TK;
        const int k0 = row0 % TK;           // multiple of 16 -> float4 aligned
        float* dstBase = g_kprojT + (size_t)b * HH * TK + k0;
#pragma unroll
        for (int i = 0; i < 4; i++) {
            int idx = tid + i * 256;        // [0,1024)
            int h = idx >> 2, seg = idx & 3;
            int rb = seg * 4;
            float4 v;
            v.x = tsm[(rb + 0) * HH + h];
            v.y = tsm[(rb + 1) * HH + h];
            v.z = tsm[(rb + 2) * HH + h];
            v.w = tsm[(rb + 3) * HH + h];
            ((float4*)(dstBase + (size_t)h * TK))[seg] = v;
        }
    }
}

// ---------------------------------------------------------------------------
// Kernel 2: fused scores + masked softmax + attn @ values.
// One block per (b, 4-query tile): 512 blocks x 256 threads, thread = k.
// K-proj read directly from global (h-major -> coalesced, L2-resident);
// no smem staging, no barriers in the hot loop. Q-tile + wv broadcast smem.
// ---------------------------------------------------------------------------
__global__ __launch_bounds__(256) void attn_kernel(
    const float* __restrict__ values, const int* __restrict__ valid_lens,
    const float* __restrict__ wv, float* __restrict__ out)
{
    __shared__ float  qsm[QT][HH];     // 4 KB
    __shared__ float  wvs[HH];         // 1 KB
    __shared__ float  scr[QT][264];    // 4.1 KB
    __shared__ float4 attnT[TK];       // 4 KB

    const int tid = threadIdx.x;
    const int b  = blockIdx.x >> 5;
    const int qt = blockIdx.x & 31;

    // stage q tile (1024 floats = 256 float4) + wv
    ((float4*)qsm)[tid] = ((const float4*)(g_qproj + (size_t)(b * TQ + qt * QT) * HH))[tid];
    if (tid < 64) ((float4*)wvs)[tid] = ((const float4*)wv)[tid];
    __syncthreads();

    const float* kT = g_kprojT + (size_t)b * HH * TK + tid;

    float acc[QT] = {0.f, 0.f, 0.f, 0.f};

#pragma unroll 2
    for (int h0 = 0; h0 < HH; h0 += 8) {
        float kv[8];
#pragma unroll
        for (int j = 0; j < 8; j++)
            kv[j] = kT[(size_t)(h0 + j) * TK];     // coalesced, MLP=8
#pragma unroll
        for (int j = 0; j < 8; j++) {
            const float w = wvs[h0 + j];           // broadcast
            acc[0] += w * tanh_fast(qsm[0][h0 + j] + kv[j]);
            acc[1] += w * tanh_fast(qsm[1][h0 + j] + kv[j]);
            acc[2] += w * tanh_fast(qsm[2][h0 + j] + kv[j]);
            acc[3] += w * tanh_fast(qsm[3][h0 + j] + kv[j]);
        }
    }

    // mask + stage scores
    const int valid = valid_lens[b];
    const bool on = (tid < valid);
#pragma unroll
    for (int qi = 0; qi < QT; qi++) scr[qi][tid] = on ? acc[qi] : NEGV;
    __syncthreads();

    // per-warp softmax: warp w handles query row w
    const int warp = tid >> 5, lane = tid & 31;
    if (warp < QT) {
        float v[8];
        float m = -3.0e38f;
#pragma unroll
        for (int j = 0; j < 8; j++) {
            v[j] = scr[warp][lane + 32 * j];
            m = fmaxf(m, v[j]);
        }
#pragma unroll
        for (int o = 16; o > 0; o >>= 1) m = fmaxf(m, __shfl_xor_sync(0xffffffffu, m, o));
        float s = 0.f;
#pragma unroll
        for (int j = 0; j < 8; j++) { v[j] = __expf(v[j] - m); s += v[j]; }
#pragma unroll
        for (int o = 16; o > 0; o >>= 1) s += __shfl_xor_sync(0xffffffffu, s, o);
        const float inv = 1.f / s;
        float* at = (float*)attnT;
#pragma unroll
        for (int j = 0; j < 8; j++) at[(lane + 32 * j) * 4 + warp] = v[j] * inv;
    }
    __syncthreads();

    // AV: thread = value column. 1 coalesced LDG + 1 broadcast LDS.128 + 4 FMA / k.
    float o4[QT] = {0.f, 0.f, 0.f, 0.f};
    const float* vp = values + (size_t)b * TK * DV + tid;
#pragma unroll 4
    for (int k = 0; k < TK; k++) {
        float vv = vp[(size_t)k * DV];
        float4 a = attnT[k];
        o4[0] += a.x * vv;
        o4[1] += a.y * vv;
        o4[2] += a.z * vv;
        o4[3] += a.w * vv;
    }
    float* op = out + (size_t)(b * TQ + qt * QT) * DV + tid;
#pragma unroll
    for (int qi = 0; qi < QT; qi++) op[(size_t)qi * DV] = o4[qi];
}

// ---------------------------------------------------------------------------
extern "C" void kernel_launch(void* const* d_in, const int* in_sizes, int n_in,
                              void* d_out, int out_size) {
    const float* queries    = (const float*)d_in[0];
    const float* keys       = (const float*)d_in[1];
    const float* values     = (const float*)d_in[2];
    const int*   valid_lens = (const int*)  d_in[3];
    const float* wq         = (const float*)d_in[4];
    const float* wk         = (const float*)d_in[5];
    const float* wv         = (const float*)d_in[6];
    float* out = (float*)d_out;

    proj_kernel<<<384, 256>>>(queries, keys, wq, wk);
    attn_kernel<<<NB * (TQ / QT), 256>>>(values, valid_lens, wv, out);
}